// round 7
// baseline (speedup 1.0000x reference)
#include <cuda_runtime.h>
#include <cuda_bf16.h>
#include <stdint.h>

#define BB 64
#define CC 3
#define JJ 11
#define TT 512
#define CO 128
#define NPTS (BB*JJ*TT)      /* 360448 */
#define SIGC 84
#define K1A 168
#define K2A 256
#define NT2 256              /* points per GEMM CTA tile */
#define GRIDG2 (NPTS/NT2)    /* 1408 gemm tiles */
#define RAWG (BB*JJ)         /* 704 raw-conv CTAs */
#define KS 32                /* GEMM k-chunk */

// ---------------- static scratch ----------------
__device__ uint32_t g_Spk[K1A * NPTS];       // sig packed (bf16 hi | bf16 lo<<16), [k][p]
__device__ float g_UV[(size_t)K2A * NPTS];   // rows 0..127 = U, 128..255 = V
__device__ float g_F[(size_t)CO * NPTS];     // fus pre-BN, channel-major
__device__ __nv_bfloat16 g_Aps_hi[6*4096],  g_Aps_lo[6*4096];   // [kc32][o][k32]
__device__ __nv_bfloat16 g_Afus_hi[8*4096], g_Afus_lo[8*4096];
__device__ float g_pU[RAWG*CO],    g_pUQ[RAWG*CO];
__device__ float g_pV[GRIDG2*CO],  g_pVQ[GRIDG2*CO];
__device__ float g_pF[GRIDG2*CO],  g_pFQ[GRIDG2*CO];
__device__ float g_sc1[K2A], g_bi1[K2A];
__device__ float g_sc2[CO],  g_bi2[CO];

// ---------------- PTX helpers (sm_80-level) ----------------
__device__ __forceinline__ uint32_t smem_u32(const void* p) {
    uint32_t a;
    asm("{ .reg .u64 t; cvta.to.shared.u64 t, %1; cvt.u32.u64 %0, t; }" : "=r"(a) : "l"(p));
    return a;
}
__device__ __forceinline__ void ldsm_x4(uint32_t (&r)[4], uint32_t addr) {
    asm volatile("ldmatrix.sync.aligned.m8n8.x4.shared.b16 {%0,%1,%2,%3}, [%4];"
        : "=r"(r[0]), "=r"(r[1]), "=r"(r[2]), "=r"(r[3]) : "r"(addr));
}
__device__ __forceinline__ void ldsm_x2_t(uint32_t (&r)[2], uint32_t addr) {
    asm volatile("ldmatrix.sync.aligned.m8n8.x2.trans.shared.b16 {%0,%1}, [%2];"
        : "=r"(r[0]), "=r"(r[1]) : "r"(addr));
}
__device__ __forceinline__ void mma_bf16(float (&d)[4], const uint32_t (&a)[4],
                                         const uint32_t (&b)[2]) {
    asm volatile("mma.sync.aligned.m16n8k16.row.col.f32.bf16.bf16.f32 "
        "{%0,%1,%2,%3}, {%4,%5,%6,%7}, {%8,%9}, {%0,%1,%2,%3};"
        : "+f"(d[0]), "+f"(d[1]), "+f"(d[2]), "+f"(d[3])
        : "r"(a[0]), "r"(a[1]), "r"(a[2]), "r"(a[3]), "r"(b[0]), "r"(b[1]));
}
__device__ __forceinline__ void cp16(uint32_t dst, const void* src, uint32_t sz) {
    asm volatile("cp.async.cg.shared.global [%0], [%1], 16, %2;"
        :: "r"(dst), "l"(src), "r"(sz));
}
#define CP_COMMIT() asm volatile("cp.async.commit_group;")
#define CP_WAIT1()  asm volatile("cp.async.wait_group 1;")
#define CP_WAIT2()  asm volatile("cp.async.wait_group 2;")

__device__ __forceinline__ uint32_t pack_hi(float a, float b, uint32_t& lo) {
    __nv_bfloat16 ha = __float2bfloat16(a), hb = __float2bfloat16(b);
    __nv_bfloat16 la = __float2bfloat16(a - __bfloat162float(ha));
    __nv_bfloat16 lb = __float2bfloat16(b - __bfloat162float(hb));
    lo = (uint32_t)__bfloat16_as_ushort(la) | ((uint32_t)__bfloat16_as_ushort(lb) << 16);
    return (uint32_t)__bfloat16_as_ushort(ha) | ((uint32_t)__bfloat16_as_ushort(hb) << 16);
}
__device__ __forceinline__ uint32_t pack1(float v) {
    __nv_bfloat16 h = __float2bfloat16(v);
    __nv_bfloat16 l = __float2bfloat16(v - __bfloat162float(h));
    return (uint32_t)__bfloat16_as_ushort(h) | ((uint32_t)__bfloat16_as_ushort(l) << 16);
}

// SMEM layout (bytes):
// A: 2 stages x 2 planes x (128 rows x 80B)
#define OFF_A(s,pl)  ((s)*20480 + (pl)*10240)
// raw B: 3 stages x (32 rows x 1024B)
#define OFF_RAW(r)   (40960 + (r)*32768)
// conv B: 2 stages x 2 planes x (32 rows x 528B)
#define OFF_B(s,pl)  (139264 + (s)*33792 + (pl)*16896)
#define OFF_SC 206848
#define OFF_BI 207872
#define SMEM_G2 208896

// ---------------- depth-3 signature Chen step (c = 4) ----------------
__device__ __forceinline__ void sig_step(float S1[4], float S2[16], float S3[64],
                                         const float d[4]) {
    float dd[16];
#pragma unroll
    for (int i = 0; i < 4; i++)
#pragma unroll
        for (int j = 0; j < 4; j++) dd[i*4+j] = d[i]*d[j];
    float a[4];
#pragma unroll
    for (int i = 0; i < 4; i++) a[i] = 0.5f*S1[i] + d[i]*(1.0f/6.0f);
#pragma unroll
    for (int i = 0; i < 4; i++)
#pragma unroll
        for (int j = 0; j < 4; j++)
#pragma unroll
            for (int k = 0; k < 4; k++)
                S3[i*16+j*4+k] += S2[i*4+j]*d[k] + a[i]*dd[j*4+k];
#pragma unroll
    for (int i = 0; i < 4; i++)
#pragma unroll
        for (int j = 0; j < 4; j++)
            S2[i*4+j] += S1[i]*d[j] + 0.5f*dd[i*4+j];
#pragma unroll
    for (int i = 0; i < 4; i++) S1[i] += d[i];
}

__device__ __forceinline__ void sig_write(int rowbase, int p,
                                          const float S1[4], const float S2[16],
                                          const float S3[64]) {
#pragma unroll
    for (int i = 0; i < 4; i++)  g_Spk[(rowbase + i)      * NPTS + p] = pack1(S1[i]);
#pragma unroll
    for (int i = 0; i < 16; i++) g_Spk[(rowbase + 4 + i)  * NPTS + p] = pack1(S2[i]);
#pragma unroll
    for (int i = 0; i < 64; i++) g_Spk[(rowbase + 20 + i) * NPTS + p] = pack1(S3[i]);
}

// ---------------- K1: signatures ----------------
__global__ void k_sig(const float* __restrict__ x, const int* __restrict__ path) {
    int p = blockIdx.x * blockDim.x + threadIdx.x;
    if (p >= NPTS) return;
    int t  = p & (TT - 1);
    int bj = p >> 9;
    int j  = bj % JJ;
    int b  = bj / JJ;
    const float* xb = x + (size_t)b * CC * JJ * TT;

    float S1[4], S2[16], S3[64];
    float prev[3], cur[3], d[4];

#pragma unroll
    for (int i = 0; i < 4; i++)  S1[i] = 0.f;
#pragma unroll
    for (int i = 0; i < 16; i++) S2[i] = 0.f;
#pragma unroll
    for (int i = 0; i < 64; i++) S3[i] = 0.f;

    int j0 = path[j*3+0], j1 = path[j*3+1], j2 = path[j*3+2];
#pragma unroll
    for (int c = 0; c < 3; c++) prev[c] = xb[(c*JJ + j0)*TT + t];
    d[0] = 0.f; d[1] = prev[0]; d[2] = prev[1]; d[3] = prev[2];
    sig_step(S1, S2, S3, d);
#pragma unroll
    for (int c = 0; c < 3; c++) cur[c] = xb[(c*JJ + j1)*TT + t];
    d[0] = 0.5f;
#pragma unroll
    for (int c = 0; c < 3; c++) { d[c+1] = cur[c] - prev[c]; prev[c] = cur[c]; }
    sig_step(S1, S2, S3, d);
#pragma unroll
    for (int c = 0; c < 3; c++) cur[c] = xb[(c*JJ + j2)*TT + t];
    d[0] = 0.5f;
#pragma unroll
    for (int c = 0; c < 3; c++) d[c+1] = cur[c] - prev[c];
    sig_step(S1, S2, S3, d);
    sig_write(0, p, S1, S2, S3);

#pragma unroll
    for (int i = 0; i < 4; i++)  S1[i] = 0.f;
#pragma unroll
    for (int i = 0; i < 16; i++) S2[i] = 0.f;
#pragma unroll
    for (int i = 0; i < 64; i++) S3[i] = 0.f;

#pragma unroll
    for (int l = 0; l < 7; l++) {
        int tc = t + l - 3;
        tc = tc < 0 ? 0 : (tc > TT-1 ? TT-1 : tc);
#pragma unroll
        for (int c = 0; c < 3; c++) cur[c] = xb[(c*JJ + j)*TT + tc];
        if (l == 0) {
            d[0] = 0.f;
#pragma unroll
            for (int c = 0; c < 3; c++) d[c+1] = cur[c];
        } else {
            d[0] = 1.0f/6.0f;
#pragma unroll
            for (int c = 0; c < 3; c++) d[c+1] = cur[c] - prev[c];
        }
#pragma unroll
        for (int c = 0; c < 3; c++) prev[c] = cur[c];
        sig_step(S1, S2, S3, d);
    }
    sig_write(SIGC, p, S1, S2, S3);
}

// ---------------- K2: raw conv + bias + fused BN partials ----------------
__global__ void k_raw(const float* __restrict__ x, const float* __restrict__ w,
                      const float* __restrict__ b) {
    __shared__ float xs[3][TT + 2];
    __shared__ float ws[CO * 9];
    __shared__ float bs[CO];
    int bj = blockIdx.x;
    int j = bj % JJ, bb = bj / JJ;
    int tid = threadIdx.x;
    int warp = tid >> 5, lane = tid & 31;

    for (int i = tid; i < 3*(TT+2); i += 256) {
        int c = i / (TT+2), tt = i % (TT+2);
        xs[c][tt] = (tt >= 1 && tt <= TT) ? x[((bb*3 + c)*JJ + j)*TT + tt - 1] : 0.f;
    }
    for (int i = tid; i < CO*9; i += 256) ws[i] = w[i];
    if (tid < CO) bs[tid] = b[tid];
    __syncthreads();

    int pbase = bj * TT;
#pragma unroll 1
    for (int oi = 0; oi < 16; oi++) {
        int o = warp*16 + oi;
        float wr[9];
#pragma unroll
        for (int i = 0; i < 9; i++) wr[i] = ws[o*9 + i];
        float bo = bs[o];
        float s = 0.f, q = 0.f;
        float* orow = g_UV + (size_t)o*NPTS + pbase;
#pragma unroll
        for (int i = 0; i < 16; i++) {
            int t = i*32 + lane;
            float a = bo;
#pragma unroll
            for (int c = 0; c < 3; c++)
#pragma unroll
                for (int kw = 0; kw < 3; kw++)
                    a = fmaf(xs[c][t + kw], wr[c*3 + kw], a);
            orow[t] = a;
            s += a; q += a*a;
        }
#pragma unroll
        for (int d = 16; d; d >>= 1) {
            s += __shfl_xor_sync(0xffffffffu, s, d);
            q += __shfl_xor_sync(0xffffffffu, q, d);
        }
        if (lane == 0) { g_pU[bj*CO + o] = s; g_pUQ[bj*CO + o] = q; }
    }
}

// ---------------- prep: bf16 hi/lo weight images, [kc32][o][k32] ----------------
__global__ void k_prep(const float* __restrict__ psw, const float* __restrict__ fusw) {
    int which = blockIdx.x;
    const float* W = which ? fusw : psw;
    int K  = which ? 256 : 168;
    int KP = which ? 256 : 192;
    __nv_bfloat16* AH = which ? g_Afus_hi : g_Aps_hi;
    __nv_bfloat16* AL = which ? g_Afus_lo : g_Aps_lo;
    for (int idx = threadIdx.x; idx < 128*KP; idx += blockDim.x) {
        int o = idx / KP, k = idx % KP;
        float v = (k < K) ? W[o*K + k] : 0.f;
        __nv_bfloat16 h = __float2bfloat16(v);
        __nv_bfloat16 l = __float2bfloat16(v - __bfloat162float(h));
        int kc = k >> 5, kk = k & 31;
        AH[kc*4096 + o*32 + kk] = h;
        AL[kc*4096 + o*32 + kk] = l;
    }
}

// ---------------- GEMM building blocks ----------------
__device__ __forceinline__ void issueA2(int c, int tid, uint32_t sb,
        const __nv_bfloat16* __restrict__ Ahg, const __nv_bfloat16* __restrict__ Alg) {
#pragma unroll
    for (int i = 0; i < 2; i++) {
        int m = tid + i*512;
        int plane = m >> 9, mm = m & 511;
        int o = mm >> 2, kq = mm & 3;
        const __nv_bfloat16* src = (plane ? Alg : Ahg) + c*4096 + o*32 + kq*8;
        cp16(sb + OFF_A(c&1, plane) + o*80 + kq*16, src, 16);
    }
}
__device__ __forceinline__ void issueRaw2(int c, int tid, uint32_t sb,
        const char* __restrict__ Bg, int kact, int p0) {
#pragma unroll
    for (int i = 0; i < 4; i++) {
        int m = tid + i*512;
        int kl = m >> 6, pseg = m & 63;
        int kg = c*KS + kl;
        int ok = kg < kact;
        const char* src = Bg + ((size_t)(ok ? kg : 0)*NPTS + p0 + pseg*4)*4;
        cp16(sb + OFF_RAW(c%3) + kl*1024 + pseg*16, src, ok ? 16u : 0u);
    }
}
// convert half of chunk cc: raw[cc%3] -> Bconv[cc&1]
__device__ __forceinline__ void conv_half(int mode, int cc, int half, int tid,
        char* smc, const float* s_sc, const float* s_bi) {
    const char* raw = smc + OFF_RAW(cc % 3);
    char* bhp = smc + OFF_B(cc & 1, 0);
    char* blp = smc + OFF_B(cc & 1, 1);
#pragma unroll
    for (int g = 0; g < 2; g++) {
        int m = tid + (half*2 + g)*512;
        int kl = m >> 6, p4 = (m & 63) << 2;
        uint2 h, l;
        if (mode) {
            float4 v = *(const float4*)(raw + kl*1024 + p4*4);
            int kg = cc*KS + kl;
            float sc = s_sc[kg], bi = s_bi[kg];
            v.x = fmaxf(fmaf(v.x, sc, bi), 0.f);
            v.y = fmaxf(fmaf(v.y, sc, bi), 0.f);
            v.z = fmaxf(fmaf(v.z, sc, bi), 0.f);
            v.w = fmaxf(fmaf(v.w, sc, bi), 0.f);
            h.x = pack_hi(v.x, v.y, l.x);
            h.y = pack_hi(v.z, v.w, l.y);
        } else {
            uint4 v = *(const uint4*)(raw + kl*1024 + p4*4);
            h.x = __byte_perm(v.x, v.y, 0x5410); l.x = __byte_perm(v.x, v.y, 0x7632);
            h.y = __byte_perm(v.z, v.w, 0x5410); l.y = __byte_perm(v.z, v.w, 0x7632);
        }
        *(uint2*)(bhp + kl*528 + p4*2) = h;
        *(uint2*)(blp + kl*528 + p4*2) = l;
    }
}

// ---------------- pipelined GEMM: D[128ch][256pts]/CTA, 512 thr ----------------
__global__ void __launch_bounds__(512, 1) k_gemm_tc(int mode, const float* __restrict__ bias) {
    extern __shared__ char smc[];
    __shared__ float sS[CO], sQ[CO];
    uint32_t sb = smem_u32(smc);
    float* s_sc = (float*)(smc + OFF_SC);
    float* s_bi = (float*)(smc + OFF_BI);

    int tid = threadIdx.x;
    int warp = tid >> 5, lane = tid & 31;
    int wm = (warp >> 3) * 64;
    int wn = (warp & 7) * 32;
    int p0 = blockIdx.x * NT2;

    int kact, kchunks;
    const __nv_bfloat16 *Ahg, *Alg;
    const char* Bg;
    float *Out, *pS, *pQ;
    if (mode == 0) {
        kact = K1A; kchunks = 6;
        Ahg = g_Aps_hi; Alg = g_Aps_lo; Bg = (const char*)g_Spk;
        Out = g_UV + (size_t)CO*NPTS; pS = g_pV; pQ = g_pVQ;
    } else {
        kact = K2A; kchunks = 8;
        Ahg = g_Afus_hi; Alg = g_Afus_lo; Bg = (const char*)g_UV;
        Out = g_F; pS = g_pF; pQ = g_pFQ;
    }

    if (mode)
        for (int i = tid; i < K2A; i += 512) { s_sc[i] = g_sc1[i]; s_bi[i] = g_bi1[i]; }
    if (tid < CO) { sS[tid] = 0.f; sQ[tid] = 0.f; }
    __syncthreads();   // s_sc visible before any conversion

    float acc[4][4][4];
#pragma unroll
    for (int i = 0; i < 4; i++)
#pragma unroll
        for (int j = 0; j < 4; j++)
#pragma unroll
            for (int r = 0; r < 4; r++) acc[i][j][r] = 0.f;

    // ---- prologue: G0={A0,raw0} G1={A1,raw1} G2={raw2} ----
    issueA2(0, tid, sb, Ahg, Alg); issueRaw2(0, tid, sb, Bg, kact, p0); CP_COMMIT();
    issueA2(1, tid, sb, Ahg, Alg); issueRaw2(1, tid, sb, Bg, kact, p0); CP_COMMIT();
    issueRaw2(2, tid, sb, Bg, kact, p0); CP_COMMIT();
    CP_WAIT2();
    __syncthreads();
    conv_half(mode, 0, 0, tid, smc, s_sc, s_bi);
    conv_half(mode, 0, 1, tid, smc, s_sc, s_bi);
    __syncthreads();

    for (int c = 0; c < kchunks; c++) {
        CP_WAIT1();
        __syncthreads();     // A[c], raw[c+1] visible; Bconv[c&1] converted
        int s = c & 1;
        int do_conv = (c + 1 < kchunks);
#pragma unroll
        for (int ks = 0; ks < 2; ks++) {
            if (do_conv) conv_half(mode, c+1, ks, tid, smc, s_sc, s_bi);
            int k0 = ks * 16;
            uint32_t ah[4][4], al[4][4];
#pragma unroll
            for (int i = 0; i < 4; i++) {
                uint32_t off = (uint32_t)((wm + i*16 + (lane & 15))*80
                                        + k0*2 + (lane >> 4)*16);
                ldsm_x4(ah[i], sb + OFF_A(s,0) + off);
                ldsm_x4(al[i], sb + OFF_A(s,1) + off);
            }
#pragma unroll
            for (int j = 0; j < 4; j++) {
                uint32_t bh[2], bl[2];
                uint32_t boff = (uint32_t)((k0 + (lane & 15))*528 + (wn + j*8)*2);
                ldsm_x2_t(bh, sb + OFF_B(s,0) + boff);
                ldsm_x2_t(bl, sb + OFF_B(s,1) + boff);
#pragma unroll
                for (int i = 0; i < 4; i++) {
                    mma_bf16(acc[i][j], ah[i], bh);
                    mma_bf16(acc[i][j], ah[i], bl);
                    mma_bf16(acc[i][j], al[i], bh);
                }
            }
        }
        __syncthreads();     // MMA(c) + conversion(c+1) done before buffer reuse
        if (c + 2 < kchunks) issueA2(c+2, tid, sb, Ahg, Alg);
        if (c + 3 < kchunks) issueRaw2(c+3, tid, sb, Bg, kact, p0);
        CP_COMMIT();
    }

    // ---- epilogue: bias, store channel-major, fused BN partials ----
#pragma unroll
    for (int i = 0; i < 4; i++) {
        int c0 = wm + i*16 + (lane >> 2);
        int c1 = c0 + 8;
        float b0 = bias[c0], b1 = bias[c1];
        float s0 = 0.f, q0 = 0.f, s1 = 0.f, q1 = 0.f;
#pragma unroll
        for (int j = 0; j < 4; j++) {
            float v00 = acc[i][j][0] + b0, v01 = acc[i][j][1] + b0;
            float v10 = acc[i][j][2] + b1, v11 = acc[i][j][3] + b1;
            int p = p0 + wn + j*8 + ((lane & 3) << 1);
            *(float2*)&Out[(size_t)c0*NPTS + p] = make_float2(v00, v01);
            *(float2*)&Out[(size_t)c1*NPTS + p] = make_float2(v10, v11);
            s0 += v00 + v01; q0 += v00*v00 + v01*v01;
            s1 += v10 + v11; q1 += v10*v10 + v11*v11;
        }
#pragma unroll
        for (int d = 1; d < 4; d <<= 1) {
            s0 += __shfl_xor_sync(0xffffffffu, s0, d);
            q0 += __shfl_xor_sync(0xffffffffu, q0, d);
            s1 += __shfl_xor_sync(0xffffffffu, s1, d);
            q1 += __shfl_xor_sync(0xffffffffu, q1, d);
        }
        if ((lane & 3) == 0) {
            atomicAdd(&sS[c0], s0); atomicAdd(&sQ[c0], q0);
            atomicAdd(&sS[c1], s1); atomicAdd(&sQ[c1], q1);
        }
    }
    __syncthreads();
    if (tid < CO) {
        pS[blockIdx.x*CO + tid] = sS[tid];
        pQ[blockIdx.x*CO + tid] = sQ[tid];
    }
}

// ---------------- finalize BN affines ----------------
__global__ void k_fin1(const float* __restrict__ rg, const float* __restrict__ rb,
                       const float* __restrict__ pg, const float* __restrict__ pb) {
    int c = blockIdx.x;   // 0..255
    float s = 0.f, q = 0.f;
    if (c < CO) {
        for (int i = threadIdx.x; i < RAWG; i += 128) { s += g_pU[i*CO + c]; q += g_pUQ[i*CO + c]; }
    } else {
        int cc = c - CO;
        for (int i = threadIdx.x; i < GRIDG2; i += 128) { s += g_pV[i*CO + cc]; q += g_pVQ[i*CO + cc]; }
    }
    __shared__ float sh[256];
    sh[threadIdx.x] = s; sh[128 + threadIdx.x] = q;
    __syncthreads();
    for (int st = 64; st; st >>= 1) {
        if (threadIdx.x < st) {
            sh[threadIdx.x]       += sh[threadIdx.x + st];
            sh[128 + threadIdx.x] += sh[128 + threadIdx.x + st];
        }
        __syncthreads();
    }
    if (threadIdx.x == 0) {
        float mean = sh[0] / (float)NPTS;
        float var  = sh[128] / (float)NPTS - mean*mean;
        float rstd = rsqrtf(var + 1e-5f);
        float g  = (c < CO) ? rg[c] : pg[c - CO];
        float be = (c < CO) ? rb[c] : pb[c - CO];
        g_sc1[c] = rstd * g;
        g_bi1[c] = be - mean * rstd * g;
    }
}

__global__ void k_fin2(const float* __restrict__ fg, const float* __restrict__ fb) {
    int c = blockIdx.x;   // 0..127
    float s = 0.f, q = 0.f;
    for (int i = threadIdx.x; i < GRIDG2; i += 128) { s += g_pF[i*CO + c]; q += g_pFQ[i*CO + c]; }
    __shared__ float sh[256];
    sh[threadIdx.x] = s; sh[128 + threadIdx.x] = q;
    __syncthreads();
    for (int st = 64; st; st >>= 1) {
        if (threadIdx.x < st) {
            sh[threadIdx.x]       += sh[threadIdx.x + st];
            sh[128 + threadIdx.x] += sh[128 + threadIdx.x + st];
        }
        __syncthreads();
    }
    if (threadIdx.x == 0) {
        float mean = sh[0] / (float)NPTS;
        float var  = sh[128] / (float)NPTS - mean*mean;
        float rstd = rsqrtf(var + 1e-5f);
        g_sc2[c] = rstd * fg[c];
        g_bi2[c] = fb[c] - mean * rstd * fg[c];
    }
}

// ---------------- final affine + relu + reshape (float4) ----------------
__global__ void k_out(float* __restrict__ out) {
    int e4 = blockIdx.x * 256 + threadIdx.x;
    int idx = e4 << 2;
    int o = idx / NPTS;
    int p = idx - o * NPTS;
    int t  = p & (TT - 1);
    int bj = p >> 9;
    int j  = bj % JJ;
    int b  = bj / JJ;
    float4 v = *(const float4*)&g_F[idx];
    float sc = g_sc2[o], bi = g_bi2[o];
    v.x = fmaxf(fmaf(v.x, sc, bi), 0.f);
    v.y = fmaxf(fmaf(v.y, sc, bi), 0.f);
    v.z = fmaxf(fmaf(v.z, sc, bi), 0.f);
    v.w = fmaxf(fmaf(v.w, sc, bi), 0.f);
    *(float4*)&out[((b*CO + o)*JJ + j)*TT + t] = v;
}

// ---------------- launcher ----------------
extern "C" void kernel_launch(void* const* d_in, const int* in_sizes, int n_in,
                              void* d_out, int out_size) {
    const float* x      = (const float*)d_in[0];
    const int*   path   = (const int*)  d_in[1];
    const float* raw_w  = (const float*)d_in[2];
    const float* raw_b  = (const float*)d_in[3];
    const float* raw_g  = (const float*)d_in[4];
    const float* raw_be = (const float*)d_in[5];
    const float* ps_w   = (const float*)d_in[6];
    const float* ps_b   = (const float*)d_in[7];
    const float* ps_g   = (const float*)d_in[8];
    const float* ps_be  = (const float*)d_in[9];
    const float* fus_w  = (const float*)d_in[10];
    const float* fus_b  = (const float*)d_in[11];
    const float* fus_g  = (const float*)d_in[12];
    const float* fus_be = (const float*)d_in[13];
    float* out = (float*)d_out;

    cudaFuncSetAttribute(k_gemm_tc, cudaFuncAttributeMaxDynamicSharedMemorySize, SMEM_G2);

    k_prep<<<2, 256>>>(ps_w, fus_w);
    k_sig<<<NPTS/256, 256>>>(x, path);
    k_raw<<<RAWG, 256>>>(x, raw_w, raw_b);
    k_gemm_tc<<<GRIDG2, 512, SMEM_G2>>>(0, ps_b);
    k_fin1<<<2*CO, 128>>>(raw_g, raw_be, ps_g, ps_be);
    k_gemm_tc<<<GRIDG2, 512, SMEM_G2>>>(1, fus_b);
    k_fin2<<<CO, 128>>>(fus_g, fus_be);
    k_out<<<(CO*NPTS)/1024, 256>>>(out);
}

// round 8
// speedup vs baseline: 1.0547x; 1.0547x over previous
#include <cuda_runtime.h>
#include <cuda_bf16.h>
#include <stdint.h>

#define BB 64
#define CC 3
#define JJ 11
#define TT 512
#define CO 128
#define NPTS (BB*JJ*TT)      /* 360448 = 2816*128 */
#define SIGC 84
#define K1A 168
#define K2A 256
#define NT 128               /* points per GEMM CTA tile */
#define GRIDG (NPTS/NT)      /* 2816 gemm tiles */
#define RAWG (BB*JJ)
#define KS 32

// ---------------- static scratch ----------------
__device__ __nv_bfloat16 g_Shi[(size_t)K1A * NPTS];  // sig hi plane [k][p]
__device__ __nv_bfloat16 g_Slo[(size_t)K1A * NPTS];  // sig lo plane [k][p]
__device__ float g_UV[(size_t)K2A * NPTS];           // rows 0..127 = U, 128..255 = V
__device__ float g_F[(size_t)CO * NPTS];
__device__ __nv_bfloat16 g_Aps_hi[6*4096],  g_Aps_lo[6*4096];   // [kc32][o][k32]
__device__ __nv_bfloat16 g_Afus_hi[8*4096], g_Afus_lo[8*4096];
__device__ float g_pU[RAWG*CO],   g_pUQ[RAWG*CO];
__device__ float g_pV[GRIDG*CO],  g_pVQ[GRIDG*CO];
__device__ float g_pF[GRIDG*CO],  g_pFQ[GRIDG*CO];
__device__ float g_sc1[K2A], g_bi1[K2A];
__device__ float g_sc2[CO],  g_bi2[CO];

// ---------------- PTX helpers (sm_80-level) ----------------
__device__ __forceinline__ uint32_t smem_u32(const void* p) {
    uint32_t a;
    asm("{ .reg .u64 t; cvta.to.shared.u64 t, %1; cvt.u32.u64 %0, t; }" : "=r"(a) : "l"(p));
    return a;
}
__device__ __forceinline__ void ldsm_x4(uint32_t (&r)[4], uint32_t addr) {
    asm volatile("ldmatrix.sync.aligned.m8n8.x4.shared.b16 {%0,%1,%2,%3}, [%4];"
        : "=r"(r[0]), "=r"(r[1]), "=r"(r[2]), "=r"(r[3]) : "r"(addr));
}
__device__ __forceinline__ void ldsm_x2_t(uint32_t (&r)[2], uint32_t addr) {
    asm volatile("ldmatrix.sync.aligned.m8n8.x2.trans.shared.b16 {%0,%1}, [%2];"
        : "=r"(r[0]), "=r"(r[1]) : "r"(addr));
}
__device__ __forceinline__ void mma_bf16(float (&d)[4], const uint32_t (&a)[4],
                                         const uint32_t (&b)[2]) {
    asm volatile("mma.sync.aligned.m16n8k16.row.col.f32.bf16.bf16.f32 "
        "{%0,%1,%2,%3}, {%4,%5,%6,%7}, {%8,%9}, {%0,%1,%2,%3};"
        : "+f"(d[0]), "+f"(d[1]), "+f"(d[2]), "+f"(d[3])
        : "r"(a[0]), "r"(a[1]), "r"(a[2]), "r"(a[3]), "r"(b[0]), "r"(b[1]));
}
__device__ __forceinline__ void cp16(uint32_t dst, const void* src, uint32_t sz) {
    asm volatile("cp.async.cg.shared.global [%0], [%1], 16, %2;"
        :: "r"(dst), "l"(src), "r"(sz));
}
#define CP_COMMIT() asm volatile("cp.async.commit_group;")
#define CP_WAIT1()  asm volatile("cp.async.wait_group 1;")

__device__ __forceinline__ uint32_t pack_hi(float a, float b, uint32_t& lo) {
    __nv_bfloat16 ha = __float2bfloat16(a), hb = __float2bfloat16(b);
    __nv_bfloat16 la = __float2bfloat16(a - __bfloat162float(ha));
    __nv_bfloat16 lb = __float2bfloat16(b - __bfloat162float(hb));
    lo = (uint32_t)__bfloat16_as_ushort(la) | ((uint32_t)__bfloat16_as_ushort(lb) << 16);
    return (uint32_t)__bfloat16_as_ushort(ha) | ((uint32_t)__bfloat16_as_ushort(hb) << 16);
}

// SMEM layout (bytes):
// A: single stage, 2 planes x (128 rows x 80B)
#define OFF_A(pl)    ((pl)*10240)
// raw B (fus only): 3 stages x (32 rows x 512B)
#define OFF_RAW(r)   (20480 + (r)*16384)
// conv B: 2 stages x 2 planes x (32 rows x 272B)
#define OFF_B(s,pl)  (69632 + (s)*17408 + (pl)*8704)
#define OFF_SC 104448
#define OFF_BI 105472
#define SMEM_GEMM 106496

// ---------------- depth-3 signature Chen step (c = 4) ----------------
__device__ __forceinline__ void sig_step(float S1[4], float S2[16], float S3[64],
                                         const float d[4]) {
    float dd[16];
#pragma unroll
    for (int i = 0; i < 4; i++)
#pragma unroll
        for (int j = 0; j < 4; j++) dd[i*4+j] = d[i]*d[j];
    float a[4];
#pragma unroll
    for (int i = 0; i < 4; i++) a[i] = 0.5f*S1[i] + d[i]*(1.0f/6.0f);
#pragma unroll
    for (int i = 0; i < 4; i++)
#pragma unroll
        for (int j = 0; j < 4; j++)
#pragma unroll
            for (int k = 0; k < 4; k++)
                S3[i*16+j*4+k] += S2[i*4+j]*d[k] + a[i]*dd[j*4+k];
#pragma unroll
    for (int i = 0; i < 4; i++)
#pragma unroll
        for (int j = 0; j < 4; j++)
            S2[i*4+j] += S1[i]*d[j] + 0.5f*dd[i*4+j];
#pragma unroll
    for (int i = 0; i < 4; i++) S1[i] += d[i];
}

__device__ __forceinline__ void wr1(int row, int p, float v) {
    __nv_bfloat16 h = __float2bfloat16(v);
    __nv_bfloat16 l = __float2bfloat16(v - __bfloat162float(h));
    g_Shi[(size_t)row*NPTS + p] = h;
    g_Slo[(size_t)row*NPTS + p] = l;
}
__device__ __forceinline__ void sig_write(int rowbase, int p,
                                          const float S1[4], const float S2[16],
                                          const float S3[64]) {
#pragma unroll
    for (int i = 0; i < 4; i++)  wr1(rowbase + i, p, S1[i]);
#pragma unroll
    for (int i = 0; i < 16; i++) wr1(rowbase + 4 + i, p, S2[i]);
#pragma unroll
    for (int i = 0; i < 64; i++) wr1(rowbase + 20 + i, p, S3[i]);
}

// ---------------- K1: signatures ----------------
__global__ void k_sig(const float* __restrict__ x, const int* __restrict__ path) {
    int p = blockIdx.x * blockDim.x + threadIdx.x;
    if (p >= NPTS) return;
    int t  = p & (TT - 1);
    int bj = p >> 9;
    int j  = bj % JJ;
    int b  = bj / JJ;
    const float* xb = x + (size_t)b * CC * JJ * TT;

    float S1[4], S2[16], S3[64];
    float prev[3], cur[3], d[4];

#pragma unroll
    for (int i = 0; i < 4; i++)  S1[i] = 0.f;
#pragma unroll
    for (int i = 0; i < 16; i++) S2[i] = 0.f;
#pragma unroll
    for (int i = 0; i < 64; i++) S3[i] = 0.f;

    int j0 = path[j*3+0], j1 = path[j*3+1], j2 = path[j*3+2];
#pragma unroll
    for (int c = 0; c < 3; c++) prev[c] = xb[(c*JJ + j0)*TT + t];
    d[0] = 0.f; d[1] = prev[0]; d[2] = prev[1]; d[3] = prev[2];
    sig_step(S1, S2, S3, d);
#pragma unroll
    for (int c = 0; c < 3; c++) cur[c] = xb[(c*JJ + j1)*TT + t];
    d[0] = 0.5f;
#pragma unroll
    for (int c = 0; c < 3; c++) { d[c+1] = cur[c] - prev[c]; prev[c] = cur[c]; }
    sig_step(S1, S2, S3, d);
#pragma unroll
    for (int c = 0; c < 3; c++) cur[c] = xb[(c*JJ + j2)*TT + t];
    d[0] = 0.5f;
#pragma unroll
    for (int c = 0; c < 3; c++) d[c+1] = cur[c] - prev[c];
    sig_step(S1, S2, S3, d);
    sig_write(0, p, S1, S2, S3);

#pragma unroll
    for (int i = 0; i < 4; i++)  S1[i] = 0.f;
#pragma unroll
    for (int i = 0; i < 16; i++) S2[i] = 0.f;
#pragma unroll
    for (int i = 0; i < 64; i++) S3[i] = 0.f;

#pragma unroll
    for (int l = 0; l < 7; l++) {
        int tc = t + l - 3;
        tc = tc < 0 ? 0 : (tc > TT-1 ? TT-1 : tc);
#pragma unroll
        for (int c = 0; c < 3; c++) cur[c] = xb[(c*JJ + j)*TT + tc];
        if (l == 0) {
            d[0] = 0.f;
#pragma unroll
            for (int c = 0; c < 3; c++) d[c+1] = cur[c];
        } else {
            d[0] = 1.0f/6.0f;
#pragma unroll
            for (int c = 0; c < 3; c++) d[c+1] = cur[c] - prev[c];
        }
#pragma unroll
        for (int c = 0; c < 3; c++) prev[c] = cur[c];
        sig_step(S1, S2, S3, d);
    }
    sig_write(SIGC, p, S1, S2, S3);
}

// ---------------- K2: raw conv + bias + fused BN partials ----------------
__global__ void k_raw(const float* __restrict__ x, const float* __restrict__ w,
                      const float* __restrict__ b) {
    __shared__ float xs[3][TT + 2];
    __shared__ float ws[CO * 9];
    __shared__ float bs[CO];
    int bj = blockIdx.x;
    int j = bj % JJ, bb = bj / JJ;
    int tid = threadIdx.x;
    int warp = tid >> 5, lane = tid & 31;

    for (int i = tid; i < 3*(TT+2); i += 256) {
        int c = i / (TT+2), tt = i % (TT+2);
        xs[c][tt] = (tt >= 1 && tt <= TT) ? x[((bb*3 + c)*JJ + j)*TT + tt - 1] : 0.f;
    }
    for (int i = tid; i < CO*9; i += 256) ws[i] = w[i];
    if (tid < CO) bs[tid] = b[tid];
    __syncthreads();

    int pbase = bj * TT;
#pragma unroll 1
    for (int oi = 0; oi < 16; oi++) {
        int o = warp*16 + oi;
        float wr[9];
#pragma unroll
        for (int i = 0; i < 9; i++) wr[i] = ws[o*9 + i];
        float bo = bs[o];
        float s = 0.f, q = 0.f;
        float* orow = g_UV + (size_t)o*NPTS + pbase;
#pragma unroll
        for (int i = 0; i < 16; i++) {
            int t = i*32 + lane;
            float a = bo;
#pragma unroll
            for (int c = 0; c < 3; c++)
#pragma unroll
                for (int kw = 0; kw < 3; kw++)
                    a = fmaf(xs[c][t + kw], wr[c*3 + kw], a);
            orow[t] = a;
            s += a; q += a*a;
        }
#pragma unroll
        for (int d = 16; d; d >>= 1) {
            s += __shfl_xor_sync(0xffffffffu, s, d);
            q += __shfl_xor_sync(0xffffffffu, q, d);
        }
        if (lane == 0) { g_pU[bj*CO + o] = s; g_pUQ[bj*CO + o] = q; }
    }
}

// ---------------- prep: bf16 hi/lo weight images, [kc32][o][k32] ----------------
__global__ void k_prep(const float* __restrict__ psw, const float* __restrict__ fusw) {
    int which = blockIdx.x;
    const float* W = which ? fusw : psw;
    int K  = which ? 256 : 168;
    int KP = which ? 256 : 192;
    __nv_bfloat16* AH = which ? g_Afus_hi : g_Aps_hi;
    __nv_bfloat16* AL = which ? g_Afus_lo : g_Aps_lo;
    for (int idx = threadIdx.x; idx < 128*KP; idx += blockDim.x) {
        int o = idx / KP, k = idx % KP;
        float v = (k < K) ? W[o*K + k] : 0.f;
        __nv_bfloat16 h = __float2bfloat16(v);
        __nv_bfloat16 l = __float2bfloat16(v - __bfloat162float(h));
        int kc = k >> 5, kk = k & 31;
        AH[kc*4096 + o*32 + kk] = h;
        AL[kc*4096 + o*32 + kk] = l;
    }
}

// ---------------- GEMM building blocks ----------------
__device__ __forceinline__ void issueA(int c, int tid, uint32_t sb,
        const __nv_bfloat16* __restrict__ Ahg, const __nv_bfloat16* __restrict__ Alg) {
#pragma unroll
    for (int i = 0; i < 4; i++) {
        int m = tid + i*256;
        int plane = m >> 9, mm = m & 511;
        int o = mm >> 2, kq = mm & 3;
        const __nv_bfloat16* src = (plane ? Alg : Ahg) + c*4096 + o*32 + kq*8;
        cp16(sb + OFF_A(plane) + o*80 + kq*16, src, 16);
    }
}
__device__ __forceinline__ void issueRaw(int c, int tid, uint32_t sb, int p0) {
#pragma unroll
    for (int i = 0; i < 4; i++) {
        int m = tid + i*256;
        int kg = c*KS + (m >> 5);
        const char* src = (const char*)g_UV + ((size_t)kg*NPTS + p0 + (m & 31)*4)*4;
        cp16(sb + OFF_RAW(c % 3) + m*16, src, 16);
    }
}
__device__ __forceinline__ void issueBdirect(int c, int tid, uint32_t sb, int p0) {
#pragma unroll
    for (int i = 0; i < 4; i++) {
        int m = tid + i*256;
        int plane = m >> 9, mm = m & 511;
        int kl = mm >> 4, pseg = mm & 15;
        int kg = c*KS + kl;
        int ok = kg < K1A;
        const __nv_bfloat16* src = (plane ? g_Slo : g_Shi)
                                 + (size_t)(ok ? kg : 0)*NPTS + p0 + pseg*8;
        cp16(sb + OFF_B(c & 1, plane) + kl*272 + pseg*16, src, ok ? 16u : 0u);
    }
}
// convert half of fus chunk cc: raw[cc%3] -> conv[cc&1]
__device__ __forceinline__ void conv_half(int cc, int half, int tid,
        char* smc, const float* s_sc, const float* s_bi) {
    const char* raw = smc + OFF_RAW(cc % 3);
    char* bhp = smc + OFF_B(cc & 1, 0);
    char* blp = smc + OFF_B(cc & 1, 1);
#pragma unroll
    for (int g = 0; g < 2; g++) {
        int m = tid + (half*2 + g)*256;
        int kl = m >> 5, p4 = (m & 31) << 2;
        float4 v = *(const float4*)(raw + m*16);
        int kg = cc*KS + kl;
        float sc = s_sc[kg], bi = s_bi[kg];
        v.x = fmaxf(fmaf(v.x, sc, bi), 0.f);
        v.y = fmaxf(fmaf(v.y, sc, bi), 0.f);
        v.z = fmaxf(fmaf(v.z, sc, bi), 0.f);
        v.w = fmaxf(fmaf(v.w, sc, bi), 0.f);
        uint2 h, l;
        h.x = pack_hi(v.x, v.y, l.x);
        h.y = pack_hi(v.z, v.w, l.y);
        *(uint2*)(bhp + kl*272 + p4*2) = h;
        *(uint2*)(blp + kl*272 + p4*2) = l;
    }
}

// ---------------- pipelined GEMM: D[128ch][128pts]/CTA, 256 thr, 2 CTA/SM ----------------
__global__ void __launch_bounds__(256, 2) k_gemm_tc(int mode, const float* __restrict__ bias) {
    extern __shared__ char smc[];
    __shared__ float sS[CO], sQ[CO];
    uint32_t sb = smem_u32(smc);
    float* s_sc = (float*)(smc + OFF_SC);
    float* s_bi = (float*)(smc + OFF_BI);

    int tid = threadIdx.x;
    int warp = tid >> 5, lane = tid & 31;
    int wm = (warp >> 2) * 64;
    int wn = (warp & 3) * 32;
    int p0 = blockIdx.x * NT;

    int kchunks;
    const __nv_bfloat16 *Ahg, *Alg;
    float *Out, *pS, *pQ;
    if (mode == 0) {
        kchunks = 6;
        Ahg = g_Aps_hi; Alg = g_Aps_lo;
        Out = g_UV + (size_t)CO*NPTS; pS = g_pV; pQ = g_pVQ;
    } else {
        kchunks = 8;
        Ahg = g_Afus_hi; Alg = g_Afus_lo;
        Out = g_F; pS = g_pF; pQ = g_pFQ;
    }

    if (mode)
        for (int i = tid; i < K2A; i += 256) { s_sc[i] = g_sc1[i]; s_bi[i] = g_bi1[i]; }
    if (tid < CO) { sS[tid] = 0.f; sQ[tid] = 0.f; }
    __syncthreads();

    float acc[4][4][4];
#pragma unroll
    for (int i = 0; i < 4; i++)
#pragma unroll
        for (int j = 0; j < 4; j++)
#pragma unroll
            for (int r = 0; r < 4; r++) acc[i][j][r] = 0.f;

    // ---- prologue ----
    if (mode) {
        issueA(0, tid, sb, Ahg, Alg);  CP_COMMIT();
        issueRaw(0, tid, sb, p0);      CP_COMMIT();
        issueRaw(1, tid, sb, p0);      CP_COMMIT();
        issueRaw(2, tid, sb, p0);      CP_COMMIT();
        CP_WAIT1();          // A0, raw0, raw1 arrived; raw2 in flight
        __syncthreads();
        conv_half(0, 0, tid, smc, s_sc, s_bi);
        conv_half(0, 1, tid, smc, s_sc, s_bi);
        __syncthreads();
    } else {
        issueA(0, tid, sb, Ahg, Alg);  CP_COMMIT();
        issueBdirect(0, tid, sb, p0);  CP_COMMIT();
        issueBdirect(1, tid, sb, p0);  CP_COMMIT();
        CP_WAIT1();          // A0, B0 arrived; B1 in flight
        __syncthreads();
    }

    for (int c = 0; c < kchunks; c++) {
        int s = c & 1;
        int dc = mode && (c + 1 < kchunks);
#pragma unroll
        for (int ks = 0; ks < 2; ks++) {
            if (dc) conv_half(c+1, ks, tid, smc, s_sc, s_bi);
            int k0 = ks * 16;
            uint32_t ah[4][4], al[4][4];
#pragma unroll
            for (int i = 0; i < 4; i++) {
                uint32_t off = (uint32_t)((wm + i*16 + (lane & 15))*80
                                        + k0*2 + (lane >> 4)*16);
                ldsm_x4(ah[i], sb + OFF_A(0) + off);
                ldsm_x4(al[i], sb + OFF_A(1) + off);
            }
#pragma unroll
            for (int j = 0; j < 4; j++) {
                uint32_t bh[2], bl[2];
                uint32_t boff = (uint32_t)((k0 + (lane & 15))*272 + (wn + j*8)*2);
                ldsm_x2_t(bh, sb + OFF_B(s,0) + boff);
                ldsm_x2_t(bl, sb + OFF_B(s,1) + boff);
#pragma unroll
                for (int i = 0; i < 4; i++) {
                    mma_bf16(acc[i][j], ah[i], bh);
                    mma_bf16(acc[i][j], ah[i], bl);
                    mma_bf16(acc[i][j], al[i], bh);
                }
            }
        }
        __syncthreads();   // MMA(c) + conv(c+1) done; A buffer & B stage reusable
        if (c + 1 < kchunks) issueA(c+1, tid, sb, Ahg, Alg);
        CP_COMMIT();
        if (mode) { if (c + 3 < kchunks) issueRaw(c+3, tid, sb, p0); }
        else      { if (c + 2 < kchunks) issueBdirect(c+2, tid, sb, p0); }
        CP_COMMIT();
        CP_WAIT1();
        __syncthreads();
    }

    // ---- epilogue: bias, store channel-major, fused BN partials ----
#pragma unroll
    for (int i = 0; i < 4; i++) {
        int c0 = wm + i*16 + (lane >> 2);
        int c1 = c0 + 8;
        float b0 = bias[c0], b1 = bias[c1];
        float s0 = 0.f, q0 = 0.f, s1 = 0.f, q1 = 0.f;
#pragma unroll
        for (int j = 0; j < 4; j++) {
            float v00 = acc[i][j][0] + b0, v01 = acc[i][j][1] + b0;
            float v10 = acc[i][j][2] + b1, v11 = acc[i][j][3] + b1;
            int p = p0 + wn + j*8 + ((lane & 3) << 1);
            *(float2*)&Out[(size_t)c0*NPTS + p] = make_float2(v00, v01);
            *(float2*)&Out[(size_t)c1*NPTS + p] = make_float2(v10, v11);
            s0 += v00 + v01; q0 += v00*v00 + v01*v01;
            s1 += v10 + v11; q1 += v10*v10 + v11*v11;
        }
#pragma unroll
        for (int d = 1; d < 4; d <<= 1) {
            s0 += __shfl_xor_sync(0xffffffffu, s0, d);
            q0 += __shfl_xor_sync(0xffffffffu, q0, d);
            s1 += __shfl_xor_sync(0xffffffffu, s1, d);
            q1 += __shfl_xor_sync(0xffffffffu, q1, d);
        }
        if ((lane & 3) == 0) {
            atomicAdd(&sS[c0], s0); atomicAdd(&sQ[c0], q0);
            atomicAdd(&sS[c1], s1); atomicAdd(&sQ[c1], q1);
        }
    }
    __syncthreads();
    if (tid < CO) {
        pS[blockIdx.x*CO + tid] = sS[tid];
        pQ[blockIdx.x*CO + tid] = sQ[tid];
    }
}

// ---------------- finalize BN affines ----------------
__global__ void k_fin1(const float* __restrict__ rg, const float* __restrict__ rb,
                       const float* __restrict__ pg, const float* __restrict__ pb) {
    int c = blockIdx.x;   // 0..255
    float s = 0.f, q = 0.f;
    if (c < CO) {
        for (int i = threadIdx.x; i < RAWG; i += 128) { s += g_pU[i*CO + c]; q += g_pUQ[i*CO + c]; }
    } else {
        int cc = c - CO;
        for (int i = threadIdx.x; i < GRIDG; i += 128) { s += g_pV[i*CO + cc]; q += g_pVQ[i*CO + cc]; }
    }
    __shared__ float sh[256];
    sh[threadIdx.x] = s; sh[128 + threadIdx.x] = q;
    __syncthreads();
    for (int st = 64; st; st >>= 1) {
        if (threadIdx.x < st) {
            sh[threadIdx.x]       += sh[threadIdx.x + st];
            sh[128 + threadIdx.x] += sh[128 + threadIdx.x + st];
        }
        __syncthreads();
    }
    if (threadIdx.x == 0) {
        float mean = sh[0] / (float)NPTS;
        float var  = sh[128] / (float)NPTS - mean*mean;
        float rstd = rsqrtf(var + 1e-5f);
        float g  = (c < CO) ? rg[c] : pg[c - CO];
        float be = (c < CO) ? rb[c] : pb[c - CO];
        g_sc1[c] = rstd * g;
        g_bi1[c] = be - mean * rstd * g;
    }
}

__global__ void k_fin2(const float* __restrict__ fg, const float* __restrict__ fb) {
    int c = blockIdx.x;   // 0..127
    float s = 0.f, q = 0.f;
    for (int i = threadIdx.x; i < GRIDG; i += 128) { s += g_pF[i*CO + c]; q += g_pFQ[i*CO + c]; }
    __shared__ float sh[256];
    sh[threadIdx.x] = s; sh[128 + threadIdx.x] = q;
    __syncthreads();
    for (int st = 64; st; st >>= 1) {
        if (threadIdx.x < st) {
            sh[threadIdx.x]       += sh[threadIdx.x + st];
            sh[128 + threadIdx.x] += sh[128 + threadIdx.x + st];
        }
        __syncthreads();
    }
    if (threadIdx.x == 0) {
        float mean = sh[0] / (float)NPTS;
        float var  = sh[128] / (float)NPTS - mean*mean;
        float rstd = rsqrtf(var + 1e-5f);
        g_sc2[c] = rstd * fg[c];
        g_bi2[c] = fb[c] - mean * rstd * fg[c];
    }
}

// ---------------- final affine + relu + reshape (float4) ----------------
__global__ void k_out(float* __restrict__ out) {
    int e4 = blockIdx.x * 256 + threadIdx.x;
    int idx = e4 << 2;
    int o = idx / NPTS;
    int p = idx - o * NPTS;
    int t  = p & (TT - 1);
    int bj = p >> 9;
    int j  = bj % JJ;
    int b  = bj / JJ;
    float4 v = *(const float4*)&g_F[idx];
    float sc = g_sc2[o], bi = g_bi2[o];
    v.x = fmaxf(fmaf(v.x, sc, bi), 0.f);
    v.y = fmaxf(fmaf(v.y, sc, bi), 0.f);
    v.z = fmaxf(fmaf(v.z, sc, bi), 0.f);
    v.w = fmaxf(fmaf(v.w, sc, bi), 0.f);
    *(float4*)&out[((b*CO + o)*JJ + j)*TT + t] = v;
}

// ---------------- launcher ----------------
extern "C" void kernel_launch(void* const* d_in, const int* in_sizes, int n_in,
                              void* d_out, int out_size) {
    const float* x      = (const float*)d_in[0];
    const int*   path   = (const int*)  d_in[1];
    const float* raw_w  = (const float*)d_in[2];
    const float* raw_b  = (const float*)d_in[3];
    const float* raw_g  = (const float*)d_in[4];
    const float* raw_be = (const float*)d_in[5];
    const float* ps_w   = (const float*)d_in[6];
    const float* ps_b   = (const float*)d_in[7];
    const float* ps_g   = (const float*)d_in[8];
    const float* ps_be  = (const float*)d_in[9];
    const float* fus_w  = (const float*)d_in[10];
    const float* fus_b  = (const float*)d_in[11];
    const float* fus_g  = (const float*)d_in[12];
    const float* fus_be = (const float*)d_in[13];
    float* out = (float*)d_out;

    cudaFuncSetAttribute(k_gemm_tc, cudaFuncAttributeMaxDynamicSharedMemorySize, SMEM_GEMM);

    k_prep<<<2, 256>>>(ps_w, fus_w);
    k_sig<<<NPTS/256, 256>>>(x, path);
    k_raw<<<RAWG, 256>>>(x, raw_w, raw_b);
    k_gemm_tc<<<GRIDG, 256, SMEM_GEMM>>>(0, ps_b);
    k_fin1<<<2*CO, 128>>>(raw_g, raw_be, ps_g, ps_be);
    k_gemm_tc<<<GRIDG, 256, SMEM_GEMM>>>(1, fus_b);
    k_fin2<<<CO, 128>>>(fus_g, fus_be);
    k_out<<<(CO*NPTS)/1024, 256>>>(out);
}

// round 9
// speedup vs baseline: 1.3985x; 1.3259x over previous
#include <cuda_runtime.h>
#include <cuda_bf16.h>
#include <stdint.h>

#define BB 64
#define CC 3
#define JJ 11
#define TT 512
#define CO 128
#define NPTS (BB*JJ*TT)      /* 360448 = 2816*128 */
#define SIGC 84
#define K1A 168
#define K2A 256
#define NT 128
#define GRIDG (NPTS/NT)      /* 2816 */
#define RAWG (BB*JJ)
#define KS 32

// ---------------- static scratch ----------------
__device__ float g_S[(size_t)K1A * NPTS];    // sig, tf32-rounded fp32, [k][p]
__device__ float g_UV[(size_t)K2A * NPTS];   // rows 0..127 = U, 128..255 = V
__device__ float g_F[(size_t)CO * NPTS];
__device__ uint4 g_Aps[6*1024];              // A fragment images per k32 chunk
__device__ uint4 g_Afus[8*1024];
__device__ float g_pU[RAWG*CO],   g_pUQ[RAWG*CO];
__device__ float g_pV[GRIDG*CO],  g_pVQ[GRIDG*CO];
__device__ float g_pF[GRIDG*CO],  g_pFQ[GRIDG*CO];
__device__ float g_sc1[K2A], g_bi1[K2A];
__device__ float g_sc2[CO],  g_bi2[CO];

// ---------------- PTX helpers ----------------
__device__ __forceinline__ uint32_t smem_u32(const void* p) {
    uint32_t a;
    asm("{ .reg .u64 t; cvta.to.shared.u64 t, %1; cvt.u32.u64 %0, t; }" : "=r"(a) : "l"(p));
    return a;
}
__device__ __forceinline__ uint32_t tf32r(float x) {
    uint32_t u;
    asm("cvt.rna.tf32.f32 %0, %1;" : "=r"(u) : "f"(x));
    return u;
}
__device__ __forceinline__ void mma_tf32(float (&d)[4], const uint4& a,
                                         uint32_t b0, uint32_t b1) {
    asm volatile("mma.sync.aligned.m16n8k8.row.col.f32.tf32.tf32.f32 "
        "{%0,%1,%2,%3}, {%4,%5,%6,%7}, {%8,%9}, {%0,%1,%2,%3};"
        : "+f"(d[0]), "+f"(d[1]), "+f"(d[2]), "+f"(d[3])
        : "r"(a.x), "r"(a.y), "r"(a.z), "r"(a.w), "r"(b0), "r"(b1));
}
__device__ __forceinline__ void cp16(uint32_t dst, const void* src, uint32_t sz) {
    asm volatile("cp.async.cg.shared.global [%0], [%1], 16, %2;"
        :: "r"(dst), "l"(src), "r"(sz));
}
#define CP_COMMIT() asm volatile("cp.async.commit_group;")
#define CP_WAIT1()  asm volatile("cp.async.wait_group 1;")

// SMEM layout (bytes):
// A frag image: 2 stages x 16KB (1024 slots x 16B, lane-linear)
#define OFF_A(s)   ((s)*16384)
// B tf32: 2 stages x (32 rows x 544B stride; 512B data)
#define OFF_B(s)   (32768 + (s)*17408)
// raw fp32 (fus): 2 stages x (32 rows x 512B)
#define OFF_RAW(s) (67584 + (s)*16384)
#define OFF_SC 100352
#define OFF_BI 101376
#define SMEM_GEMM 102400

// ---------------- depth-3 signature Chen step (c = 4) ----------------
__device__ __forceinline__ void sig_step(float S1[4], float S2[16], float S3[64],
                                         const float d[4]) {
    float dd[16];
#pragma unroll
    for (int i = 0; i < 4; i++)
#pragma unroll
        for (int j = 0; j < 4; j++) dd[i*4+j] = d[i]*d[j];
    float a[4];
#pragma unroll
    for (int i = 0; i < 4; i++) a[i] = 0.5f*S1[i] + d[i]*(1.0f/6.0f);
#pragma unroll
    for (int i = 0; i < 4; i++)
#pragma unroll
        for (int j = 0; j < 4; j++)
#pragma unroll
            for (int k = 0; k < 4; k++)
                S3[i*16+j*4+k] += S2[i*4+j]*d[k] + a[i]*dd[j*4+k];
#pragma unroll
    for (int i = 0; i < 4; i++)
#pragma unroll
        for (int j = 0; j < 4; j++)
            S2[i*4+j] += S1[i]*d[j] + 0.5f*dd[i*4+j];
#pragma unroll
    for (int i = 0; i < 4; i++) S1[i] += d[i];
}

__device__ __forceinline__ void wr1(int row, int p, float v) {
    g_S[(size_t)row*NPTS + p] = __uint_as_float(tf32r(v));
}
__device__ __forceinline__ void sig_write(int rowbase, int p,
                                          const float S1[4], const float S2[16],
                                          const float S3[64]) {
#pragma unroll
    for (int i = 0; i < 4; i++)  wr1(rowbase + i, p, S1[i]);
#pragma unroll
    for (int i = 0; i < 16; i++) wr1(rowbase + 4 + i, p, S2[i]);
#pragma unroll
    for (int i = 0; i < 64; i++) wr1(rowbase + 20 + i, p, S3[i]);
}

// ---------------- K1: signatures ----------------
__global__ void k_sig(const float* __restrict__ x, const int* __restrict__ path) {
    int p = blockIdx.x * blockDim.x + threadIdx.x;
    if (p >= NPTS) return;
    int t  = p & (TT - 1);
    int bj = p >> 9;
    int j  = bj % JJ;
    int b  = bj / JJ;
    const float* xb = x + (size_t)b * CC * JJ * TT;

    float S1[4], S2[16], S3[64];
    float prev[3], cur[3], d[4];

#pragma unroll
    for (int i = 0; i < 4; i++)  S1[i] = 0.f;
#pragma unroll
    for (int i = 0; i < 16; i++) S2[i] = 0.f;
#pragma unroll
    for (int i = 0; i < 64; i++) S3[i] = 0.f;

    int j0 = path[j*3+0], j1 = path[j*3+1], j2 = path[j*3+2];
#pragma unroll
    for (int c = 0; c < 3; c++) prev[c] = xb[(c*JJ + j0)*TT + t];
    d[0] = 0.f; d[1] = prev[0]; d[2] = prev[1]; d[3] = prev[2];
    sig_step(S1, S2, S3, d);
#pragma unroll
    for (int c = 0; c < 3; c++) cur[c] = xb[(c*JJ + j1)*TT + t];
    d[0] = 0.5f;
#pragma unroll
    for (int c = 0; c < 3; c++) { d[c+1] = cur[c] - prev[c]; prev[c] = cur[c]; }
    sig_step(S1, S2, S3, d);
#pragma unroll
    for (int c = 0; c < 3; c++) cur[c] = xb[(c*JJ + j2)*TT + t];
    d[0] = 0.5f;
#pragma unroll
    for (int c = 0; c < 3; c++) d[c+1] = cur[c] - prev[c];
    sig_step(S1, S2, S3, d);
    sig_write(0, p, S1, S2, S3);

#pragma unroll
    for (int i = 0; i < 4; i++)  S1[i] = 0.f;
#pragma unroll
    for (int i = 0; i < 16; i++) S2[i] = 0.f;
#pragma unroll
    for (int i = 0; i < 64; i++) S3[i] = 0.f;

#pragma unroll
    for (int l = 0; l < 7; l++) {
        int tc = t + l - 3;
        tc = tc < 0 ? 0 : (tc > TT-1 ? TT-1 : tc);
#pragma unroll
        for (int c = 0; c < 3; c++) cur[c] = xb[(c*JJ + j)*TT + tc];
        if (l == 0) {
            d[0] = 0.f;
#pragma unroll
            for (int c = 0; c < 3; c++) d[c+1] = cur[c];
        } else {
            d[0] = 1.0f/6.0f;
#pragma unroll
            for (int c = 0; c < 3; c++) d[c+1] = cur[c] - prev[c];
        }
#pragma unroll
        for (int c = 0; c < 3; c++) prev[c] = cur[c];
        sig_step(S1, S2, S3, d);
    }
    sig_write(SIGC, p, S1, S2, S3);
}

// ---------------- K2: raw conv + bias + fused BN partials ----------------
__global__ void k_raw(const float* __restrict__ x, const float* __restrict__ w,
                      const float* __restrict__ b) {
    __shared__ float xs[3][TT + 2];
    __shared__ float ws[CO * 9];
    __shared__ float bs[CO];
    int bj = blockIdx.x;
    int j = bj % JJ, bb = bj / JJ;
    int tid = threadIdx.x;
    int warp = tid >> 5, lane = tid & 31;

    for (int i = tid; i < 3*(TT+2); i += 256) {
        int c = i / (TT+2), tt = i % (TT+2);
        xs[c][tt] = (tt >= 1 && tt <= TT) ? x[((bb*3 + c)*JJ + j)*TT + tt - 1] : 0.f;
    }
    for (int i = tid; i < CO*9; i += 256) ws[i] = w[i];
    if (tid < CO) bs[tid] = b[tid];
    __syncthreads();

    int pbase = bj * TT;
#pragma unroll 1
    for (int oi = 0; oi < 16; oi++) {
        int o = warp*16 + oi;
        float wr[9];
#pragma unroll
        for (int i = 0; i < 9; i++) wr[i] = ws[o*9 + i];
        float bo = bs[o];
        float s = 0.f, q = 0.f;
        float* orow = g_UV + (size_t)o*NPTS + pbase;
#pragma unroll
        for (int i = 0; i < 16; i++) {
            int t = i*32 + lane;
            float a = bo;
#pragma unroll
            for (int c = 0; c < 3; c++)
#pragma unroll
                for (int kw = 0; kw < 3; kw++)
                    a = fmaf(xs[c][t + kw], wr[c*3 + kw], a);
            orow[t] = a;
            s += a; q += a*a;
        }
#pragma unroll
        for (int d = 16; d; d >>= 1) {
            s += __shfl_xor_sync(0xffffffffu, s, d);
            q += __shfl_xor_sync(0xffffffffu, q, d);
        }
        if (lane == 0) { g_pU[bj*CO + o] = s; g_pUQ[bj*CO + o] = q; }
    }
}

// ---------------- prep: A fragment images (tf32), per-chunk slot layout ----------------
// slot = kc*1024 + g*128 + ks*32 + lane; holds {a0,a1,a2,a3} for
// rows r=g*16+lane/4 (+8), cols k=kc*32+ks*8+lane%4 (+4)
__global__ void k_prep(const float* __restrict__ psw, const float* __restrict__ fusw) {
    int which = blockIdx.x;
    const float* W = which ? fusw : psw;
    int K = which ? K2A : K1A;
    int nslot = which ? 8*1024 : 6*1024;
    uint4* A = which ? g_Afus : g_Aps;
    for (int s = threadIdx.x; s < nslot; s += blockDim.x) {
        int lane = s & 31, ks = (s >> 5) & 3, g = (s >> 7) & 7, kc = s >> 10;
        int r = g*16 + (lane >> 2);
        int kg = kc*32 + ks*8 + (lane & 3);
        float a0 = (kg < K)     ? W[r*K + kg]         : 0.f;
        float a1 = (kg < K)     ? W[(r+8)*K + kg]     : 0.f;
        float a2 = (kg+4 < K)   ? W[r*K + kg + 4]     : 0.f;
        float a3 = (kg+4 < K)   ? W[(r+8)*K + kg + 4] : 0.f;
        A[s] = make_uint4(tf32r(a0), tf32r(a1), tf32r(a2), tf32r(a3));
    }
}

// ---------------- GEMM building blocks ----------------
__device__ __forceinline__ void issueA(int c, int tid, uint32_t sb, const uint4* Aimg) {
#pragma unroll
    for (int i = 0; i < 4; i++) {
        int m = tid + i*256;
        cp16(sb + OFF_A(c & 1) + m*16, Aimg + c*1024 + m, 16);
    }
}
__device__ __forceinline__ void issueB0(int c, int tid, uint32_t sb, int p0) {
#pragma unroll
    for (int i = 0; i < 4; i++) {
        int m = tid + i*256;
        int kl = m >> 5, seg = m & 31;
        int kg = c*KS + kl;
        int ok = kg < K1A;
        const float* src = g_S + (size_t)(ok ? kg : 0)*NPTS + p0 + seg*4;
        cp16(sb + OFF_B(c & 1) + kl*544 + seg*16, src, ok ? 16u : 0u);
    }
}
__device__ __forceinline__ void issueRaw(int c, int tid, uint32_t sb, int p0) {
#pragma unroll
    for (int i = 0; i < 4; i++) {
        int m = tid + i*256;
        int kl = m >> 5, seg = m & 31;
        const float* src = g_UV + (size_t)(c*KS + kl)*NPTS + p0 + seg*4;
        cp16(sb + OFF_RAW(c & 1) + m*16, src, 16);
    }
}
// convert chunk cc (self-copied bytes only): raw[cc&1] -> B[cc&1], affine+relu+tf32
__device__ __forceinline__ void conv32(int cc, int tid, char* smc,
        const float* s_sc, const float* s_bi) {
    const char* raw = smc + OFF_RAW(cc & 1);
    char* B = smc + OFF_B(cc & 1);
#pragma unroll
    for (int i = 0; i < 4; i++) {
        int m = tid + i*256;
        int kl = m >> 5, seg = m & 31;
        float4 v = *(const float4*)(raw + m*16);
        int kg = cc*KS + kl;
        float sc = s_sc[kg], bi = s_bi[kg];
        uint4 o;
        o.x = tf32r(fmaxf(fmaf(v.x, sc, bi), 0.f));
        o.y = tf32r(fmaxf(fmaf(v.y, sc, bi), 0.f));
        o.z = tf32r(fmaxf(fmaf(v.z, sc, bi), 0.f));
        o.w = tf32r(fmaxf(fmaf(v.w, sc, bi), 0.f));
        *(uint4*)(B + kl*544 + seg*16) = o;
    }
}

// ---------------- pipelined tf32 GEMM: D[128ch][128pts]/CTA, 256 thr, 2 CTA/SM ----------------
__global__ void __launch_bounds__(256, 2) k_gemm_tc(int mode, const float* __restrict__ bias) {
    extern __shared__ char smc[];
    __shared__ float sS[CO], sQ[CO];
    uint32_t sb = smem_u32(smc);
    float* s_sc = (float*)(smc + OFF_SC);
    float* s_bi = (float*)(smc + OFF_BI);

    int tid = threadIdx.x;
    int warp = tid >> 5, lane = tid & 31;
    int wm = (warp >> 2) * 64;
    int wn = (warp & 3) * 32;
    int gbase = (warp >> 2) * 4;
    int lq = lane >> 2, lr = lane & 3;
    int p0 = blockIdx.x * NT;

    int kchunks = mode ? 8 : 6;
    const uint4* Aimg = mode ? g_Afus : g_Aps;
    float* Out = mode ? g_F : (g_UV + (size_t)CO*NPTS);
    float* pS  = mode ? g_pF : g_pV;
    float* pQ  = mode ? g_pFQ : g_pVQ;

    if (mode)
        for (int i = tid; i < K2A; i += 256) { s_sc[i] = g_sc1[i]; s_bi[i] = g_bi1[i]; }
    if (tid < CO) { sS[tid] = 0.f; sQ[tid] = 0.f; }
    __syncthreads();

    float acc[4][4][4];
#pragma unroll
    for (int i = 0; i < 4; i++)
#pragma unroll
        for (int j = 0; j < 4; j++)
#pragma unroll
            for (int r = 0; r < 4; r++) acc[i][j][r] = 0.f;

    // ---- prologue ----
    issueA(0, tid, sb, Aimg);
    if (mode) issueRaw(0, tid, sb, p0); else issueB0(0, tid, sb, p0);
    CP_COMMIT();
    issueA(1, tid, sb, Aimg);
    if (mode) issueRaw(1, tid, sb, p0); else issueB0(1, tid, sb, p0);
    CP_COMMIT();
    CP_WAIT1();                       // A0 + B0/raw0 arrived (self)
    if (mode) conv32(0, tid, smc, s_sc, s_bi);
    __syncthreads();

    for (int c = 0; c < kchunks; c++) {
        int s = c & 1;
        const char* As = smc + OFF_A(s);
        const char* Bs = smc + OFF_B(s);
        // ---- MMA chunk c: 4 k8 steps ----
#pragma unroll
        for (int ks = 0; ks < 4; ks++) {
            uint4 af[4];
#pragma unroll
            for (int i = 0; i < 4; i++)
                af[i] = *(const uint4*)(As + ((gbase + i)*4 + ks)*512 + lane*16);
#pragma unroll
            for (int j = 0; j < 4; j++) {
                const char* bp = Bs + (ks*8 + lr)*544 + (wn + j*8 + lq)*4;
                uint32_t b0 = *(const uint32_t*)bp;
                uint32_t b1 = *(const uint32_t*)(bp + 4*544);
#pragma unroll
                for (int i = 0; i < 4; i++)
                    mma_tf32(acc[i][j], af[i], b0, b1);
            }
        }
        __syncthreads();       // MMA(c) reads done; stage c&1 reusable
        if (c + 2 < kchunks) {
            issueA(c+2, tid, sb, Aimg);
            if (mode) issueRaw(c+2, tid, sb, p0); else issueB0(c+2, tid, sb, p0);
        }
        CP_COMMIT();
        CP_WAIT1();            // A(c+1) + B/raw(c+1) arrived (self)
        if (mode && c + 1 < kchunks) conv32(c+1, tid, smc, s_sc, s_bi);
        __syncthreads();       // all copies/conversions visible CTA-wide
    }

    // ---- epilogue: bias, store channel-major, fused BN partials ----
#pragma unroll
    for (int i = 0; i < 4; i++) {
        int c0 = wm + i*16 + lq;
        int c1 = c0 + 8;
        float b0 = bias[c0], b1 = bias[c1];
        float s0 = 0.f, q0 = 0.f, s1 = 0.f, q1 = 0.f;
#pragma unroll
        for (int j = 0; j < 4; j++) {
            float v00 = acc[i][j][0] + b0, v01 = acc[i][j][1] + b0;
            float v10 = acc[i][j][2] + b1, v11 = acc[i][j][3] + b1;
            int p = p0 + wn + j*8 + (lr << 1);
            *(float2*)&Out[(size_t)c0*NPTS + p] = make_float2(v00, v01);
            *(float2*)&Out[(size_t)c1*NPTS + p] = make_float2(v10, v11);
            s0 += v00 + v01; q0 += v00*v00 + v01*v01;
            s1 += v10 + v11; q1 += v10*v10 + v11*v11;
        }
#pragma unroll
        for (int d = 1; d < 4; d <<= 1) {
            s0 += __shfl_xor_sync(0xffffffffu, s0, d);
            q0 += __shfl_xor_sync(0xffffffffu, q0, d);
            s1 += __shfl_xor_sync(0xffffffffu, s1, d);
            q1 += __shfl_xor_sync(0xffffffffu, q1, d);
        }
        if (lr == 0) {
            atomicAdd(&sS[c0], s0); atomicAdd(&sQ[c0], q0);
            atomicAdd(&sS[c1], s1); atomicAdd(&sQ[c1], q1);
        }
    }
    __syncthreads();
    if (tid < CO) {
        pS[blockIdx.x*CO + tid] = sS[tid];
        pQ[blockIdx.x*CO + tid] = sQ[tid];
    }
}

// ---------------- finalize BN affines ----------------
__global__ void k_fin1(const float* __restrict__ rg, const float* __restrict__ rb,
                       const float* __restrict__ pg, const float* __restrict__ pb) {
    int c = blockIdx.x;   // 0..255
    float s = 0.f, q = 0.f;
    if (c < CO) {
        for (int i = threadIdx.x; i < RAWG; i += 128) { s += g_pU[i*CO + c]; q += g_pUQ[i*CO + c]; }
    } else {
        int cc = c - CO;
        for (int i = threadIdx.x; i < GRIDG; i += 128) { s += g_pV[i*CO + cc]; q += g_pVQ[i*CO + cc]; }
    }
    __shared__ float sh[256];
    sh[threadIdx.x] = s; sh[128 + threadIdx.x] = q;
    __syncthreads();
    for (int st = 64; st; st >>= 1) {
        if (threadIdx.x < st) {
            sh[threadIdx.x]       += sh[threadIdx.x + st];
            sh[128 + threadIdx.x] += sh[128 + threadIdx.x + st];
        }
        __syncthreads();
    }
    if (threadIdx.x == 0) {
        float mean = sh[0] / (float)NPTS;
        float var  = sh[128] / (float)NPTS - mean*mean;
        float rstd = rsqrtf(var + 1e-5f);
        float g  = (c < CO) ? rg[c] : pg[c - CO];
        float be = (c < CO) ? rb[c] : pb[c - CO];
        g_sc1[c] = rstd * g;
        g_bi1[c] = be - mean * rstd * g;
    }
}

__global__ void k_fin2(const float* __restrict__ fg, const float* __restrict__ fb) {
    int c = blockIdx.x;   // 0..127
    float s = 0.f, q = 0.f;
    for (int i = threadIdx.x; i < GRIDG; i += 128) { s += g_pF[i*CO + c]; q += g_pFQ[i*CO + c]; }
    __shared__ float sh[256];
    sh[threadIdx.x] = s; sh[128 + threadIdx.x] = q;
    __syncthreads();
    for (int st = 64; st; st >>= 1) {
        if (threadIdx.x < st) {
            sh[threadIdx.x]       += sh[threadIdx.x + st];
            sh[128 + threadIdx.x] += sh[128 + threadIdx.x + st];
        }
        __syncthreads();
    }
    if (threadIdx.x == 0) {
        float mean = sh[0] / (float)NPTS;
        float var  = sh[128] / (float)NPTS - mean*mean;
        float rstd = rsqrtf(var + 1e-5f);
        g_sc2[c] = rstd * fg[c];
        g_bi2[c] = fb[c] - mean * rstd * fg[c];
    }
}

// ---------------- final affine + relu + reshape (float4) ----------------
__global__ void k_out(float* __restrict__ out) {
    int e4 = blockIdx.x * 256 + threadIdx.x;
    int idx = e4 << 2;
    int o = idx / NPTS;
    int p = idx - o * NPTS;
    int t  = p & (TT - 1);
    int bj = p >> 9;
    int j  = bj % JJ;
    int b  = bj / JJ;
    float4 v = *(const float4*)&g_F[idx];
    float sc = g_sc2[o], bi = g_bi2[o];
    v.x = fmaxf(fmaf(v.x, sc, bi), 0.f);
    v.y = fmaxf(fmaf(v.y, sc, bi), 0.f);
    v.z = fmaxf(fmaf(v.z, sc, bi), 0.f);
    v.w = fmaxf(fmaf(v.w, sc, bi), 0.f);
    *(float4*)&out[((b*CO + o)*JJ + j)*TT + t] = v;
}

// ---------------- launcher ----------------
extern "C" void kernel_launch(void* const* d_in, const int* in_sizes, int n_in,
                              void* d_out, int out_size) {
    const float* x      = (const float*)d_in[0];
    const int*   path   = (const int*)  d_in[1];
    const float* raw_w  = (const float*)d_in[2];
    const float* raw_b  = (const float*)d_in[3];
    const float* raw_g  = (const float*)d_in[4];
    const float* raw_be = (const float*)d_in[5];
    const float* ps_w   = (const float*)d_in[6];
    const float* ps_b   = (const float*)d_in[7];
    const float* ps_g   = (const float*)d_in[8];
    const float* ps_be  = (const float*)d_in[9];
    const float* fus_w  = (const float*)d_in[10];
    const float* fus_b  = (const float*)d_in[11];
    const float* fus_g  = (const float*)d_in[12];
    const float* fus_be = (const float*)d_in[13];
    float* out = (float*)d_out;

    cudaFuncSetAttribute(k_gemm_tc, cudaFuncAttributeMaxDynamicSharedMemorySize, SMEM_GEMM);

    k_prep<<<2, 256>>>(ps_w, fus_w);
    k_sig<<<NPTS/256, 256>>>(x, path);
    k_raw<<<RAWG, 256>>>(x, raw_w, raw_b);
    k_gemm_tc<<<GRIDG, 256, SMEM_GEMM>>>(0, ps_b);
    k_fin1<<<2*CO, 128>>>(raw_g, raw_be, ps_g, ps_be);
    k_gemm_tc<<<GRIDG, 256, SMEM_GEMM>>>(1, fus_b);
    k_fin2<<<CO, 128>>>(fus_g, fus_be);
    k_out<<<(CO*NPTS)/1024, 256>>>(out);
}